// round 4
// baseline (speedup 1.0000x reference)
#include <cuda_runtime.h>
#include <cuda_bf16.h>

// Yolov1 loss, fused single pass + last-block-done final reduction.
// B=16384, S0=S1=7, NB=2, NC=20, D=30. Cells = 802816 = 3136 blocks * 256 threads.
//
// SMEM layout: cell c occupies words [c*31, c*31+30) — stride 31 (odd) makes
// per-thread scalar LDS bank-conflict-free (stride-30 was 2-way).

#define NBLOCKS 3136
#define NTHREADS 256

__device__ float g_partials[NBLOCKS];
__device__ unsigned int g_done = 0;   // atomicInc mod NBLOCKS -> self-resetting

// sigmoid(x) = 0.5*tanh(x/2) + 0.5  -> single MUFU.TANH instead of EX2+RCP
__device__ __forceinline__ float fsig(float x) {
    float t;
    asm("tanh.approx.f32 %0, %1;" : "=f"(t) : "f"(x * 0.5f));
    return fmaf(t, 0.5f, 0.5f);
}

__device__ __forceinline__ float fsqrt_a(float x) {
    float r;
    asm("sqrt.approx.f32 %0, %1;" : "=f"(r) : "f"(x));
    return r;
}

__global__ __launch_bounds__(NTHREADS)
void yolo_loss_kernel(const float* __restrict__ pred,
                      const int*   __restrict__ grid,
                      const float* __restrict__ tbox,
                      const int*   __restrict__ tcls,
                      float* __restrict__ out)
{
    // 256 cells * 31 words (30 data + 1 pad) = 7936 words = 31744 B
    __shared__ float sp[NTHREADS * 31];
    {
        const float4* src = reinterpret_cast<const float4*>(pred)
                          + (size_t)blockIdx.x * (NTHREADS * 30 / 4);   // 1920 float4/block
        #pragma unroll
        for (int i = 0; i < 8; i++) {
            const int lin = threadIdx.x + i * NTHREADS;                 // float4 idx in tile
            if (lin < NTHREADS * 30 / 4) {
                const float4 v = src[lin];
                const int w = lin * 4;                                  // logical word idx
                // padded position: w' = w + w/30  (cell stride becomes 31)
                sp[(w + 0) + (w + 0) / 30] = v.x;
                sp[(w + 1) + (w + 1) / 30] = v.y;
                sp[(w + 2) + (w + 2) / 30] = v.z;
                sp[(w + 3) + (w + 3) / 30] = v.w;
            }
        }
    }
    __syncthreads();

    const int t = blockIdx.x * NTHREADS + threadIdx.x;   // global cell index
    const float* p = sp + threadIdx.x * 31;

    const int s = t % 49;
    const float xg = (float)(s % 7);   // column
    const float yg = (float)(s / 7);   // row
    const float inv7 = 1.0f / 7.0f;

    const int   g  = grid[t];
    const float4 tb = reinterpret_cast<const float4*>(tbox)[t];
    const int   tc = tcls[t];
    const float tox = tb.x, toy = tb.y, tw = tb.z, th = tb.w;

    // sigmoids (1 MUFU each)
    const float conf0 = fsig(p[0]);
    const float conf1 = fsig(p[1]);
    float pb[2][4];
    #pragma unroll
    for (int nb = 0; nb < 2; nb++)
        #pragma unroll
        for (int k = 0; k < 4; k++)
            pb[nb][k] = fsig(p[2 + nb * 4 + k]);

    // softmax class prob at target class
    float esum = 0.0f, et = 0.0f;
    #pragma unroll
    for (int j = 0; j < 20; j++) {
        const float e = __expf(p[10 + j]);
        esum += e;
        if (j == tc) et = e;
    }
    const float cls_t = __fdividef(et, esum);

    // IOU of each predicted box vs the target box
    const float tcx = (xg + tox) * inv7;
    const float tcy = (yg + toy) * inv7;
    float iou[2];
    #pragma unroll
    for (int nb = 0; nb < 2; nb++) {
        const float pcx = (xg + pb[nb][0]) * inv7;
        const float pcy = (yg + pb[nb][1]) * inv7;
        const float pw = pb[nb][2], ph = pb[nb][3];
        const float tb_ = fminf(tcx + tw * 0.5f, pcx + pw * 0.5f)
                        - fmaxf(tcx - tw * 0.5f, pcx - pw * 0.5f);
        const float lr_ = fminf(tcy + th * 0.5f, pcy + ph * 0.5f)
                        - fmaxf(tcy - th * 0.5f, pcy - ph * 0.5f);
        const float inter = (tb_ < 0.0f || lr_ < 0.0f) ? 0.0f : tb_ * lr_;
        iou[nb] = __fdividef(inter, tw * th + pw * ph - inter);
    }

    const int best = (iou[1] > iou[0]) ? 1 : 0;
    const float iou_b  = iou[best];
    const float conf_b = best ? conf1 : conf0;
    const float b0 = pb[best][0], b1 = pb[best][1], b2 = pb[best][2], b3 = pb[best][3];

    const float d0 = b0 - tox;
    const float d1 = b1 - toy;
    const float d2 = fsqrt_a(b2) - fsqrt_a(tw);
    const float d3 = fsqrt_a(b3) - fsqrt_a(th);
    const float coord = d0 * d0 + d1 * d1 + d2 * d2 + d3 * d3;

    const float dc = conf_b - iou_b;
    const float dl = 1.0f - cls_t;
    const float obj_loss   = 5.0f * coord + dc * dc + dl * dl;
    const float noobj_loss = 0.5f * (conf0 * conf0 + conf1 * conf1);

    float v = (g == 1) ? obj_loss : noobj_loss;

    // block reduction -> g_partials[blockIdx.x]
    #pragma unroll
    for (int o = 16; o; o >>= 1) v += __shfl_down_sync(0xffffffffu, v, o);
    __shared__ float wsum[NTHREADS / 32];
    __shared__ bool s_last;
    if ((threadIdx.x & 31) == 0) wsum[threadIdx.x >> 5] = v;
    __syncthreads();
    if (threadIdx.x < NTHREADS / 32) {
        v = wsum[threadIdx.x];
        #pragma unroll
        for (int o = NTHREADS / 64; o; o >>= 1) v += __shfl_down_sync(0xffu, v, o);
        if (threadIdx.x == 0) {
            g_partials[blockIdx.x] = v;
            __threadfence();
            unsigned int prev = atomicInc(&g_done, NBLOCKS - 1);
            s_last = (prev == NBLOCKS - 1);
        }
    }
    __syncthreads();

    // Last-arriving block performs the final reduction (fixed order -> deterministic)
    if (s_last) {
        double acc = 0.0;
        for (int i = threadIdx.x; i < NBLOCKS; i += NTHREADS)
            acc += (double)g_partials[i];
        #pragma unroll
        for (int o = 16; o; o >>= 1) acc += __shfl_down_sync(0xffffffffu, acc, o);
        __shared__ double ws[NTHREADS / 32];
        if ((threadIdx.x & 31) == 0) ws[threadIdx.x >> 5] = acc;
        __syncthreads();
        if (threadIdx.x == 0) {
            double sum = 0.0;
            #pragma unroll
            for (int i = 0; i < NTHREADS / 32; i++) sum += ws[i];
            out[0] = (float)(sum / 16384.0);
        }
    }
}

extern "C" void kernel_launch(void* const* d_in, const int* in_sizes, int n_in,
                              void* d_out, int out_size)
{
    const float* pred = (const float*)d_in[0];   // (B, 1470) f32
    const int*   grid = (const int*)  d_in[1];   // (B, 7, 7) i32
    const float* tbox = (const float*)d_in[2];   // (B, 7, 7, 4) f32
    const int*   tcls = (const int*)  d_in[3];   // (B, 7, 7) i32
    float* out = (float*)d_out;

    yolo_loss_kernel<<<NBLOCKS, NTHREADS>>>(pred, grid, tbox, tcls, out);
}

// round 6
// speedup vs baseline: 1.1301x; 1.1301x over previous
#include <cuda_runtime.h>
#include <cuda_bf16.h>

// Yolov1 loss. cp.async per-warp staging, 2 tiles/warp pipeline, warp-local sync.
// B=16384, cells = 802816 = 1568 blocks * 512 cells (256 threads, 2 cells/thread).
// Cell layout: [0:2) conf, [2:10) boxes (NB,4), [10:30) class logits.

#define NBLOCKS 1568
#define NTHREADS 256
#define CELLS_PER_BLOCK 512

__device__ float g_partials[NBLOCKS];
__device__ unsigned int g_done = 0;   // atomicInc mod NBLOCKS -> self-resetting

__device__ __forceinline__ float fsig(float x) {
    float t;
    asm("tanh.approx.f32 %0, %1;" : "=f"(t) : "f"(x * 0.5f));
    return fmaf(t, 0.5f, 0.5f);
}
__device__ __forceinline__ float fsqrt_a(float x) {
    float r;
    asm("sqrt.approx.f32 %0, %1;" : "=f"(r) : "f"(x));
    return r;
}
__device__ __forceinline__ unsigned int smem_u32(const void* p) {
    return (unsigned int)__cvta_generic_to_shared(p);
}

// Compute one cell's loss term. p = 30 floats in smem (stride 30).
__device__ __forceinline__ float cell_loss(const float* __restrict__ p, int t,
                                           const int* __restrict__ grid,
                                           const float* __restrict__ tbox,
                                           const int* __restrict__ tcls)
{
    const int s = t % 49;
    const float xg = (float)(s % 7);
    const float yg = (float)(s / 7);
    const float inv7 = 1.0f / 7.0f;

    const int   g  = grid[t];
    const float4 tb = reinterpret_cast<const float4*>(tbox)[t];
    const int   tc = tcls[t];
    const float tox = tb.x, toy = tb.y, tw = tb.z, th = tb.w;

    const float conf0 = fsig(p[0]);
    const float conf1 = fsig(p[1]);
    float pb[2][4];
    #pragma unroll
    for (int nb = 0; nb < 2; nb++)
        #pragma unroll
        for (int k = 0; k < 4; k++)
            pb[nb][k] = fsig(p[2 + nb * 4 + k]);

    float esum = 0.0f, et = 0.0f;
    #pragma unroll
    for (int j = 0; j < 20; j++) {
        const float e = __expf(p[10 + j]);
        esum += e;
        if (j == tc) et = e;
    }
    const float cls_t = __fdividef(et, esum);

    const float tcx = (xg + tox) * inv7;
    const float tcy = (yg + toy) * inv7;
    float iou[2];
    #pragma unroll
    for (int nb = 0; nb < 2; nb++) {
        const float pcx = (xg + pb[nb][0]) * inv7;
        const float pcy = (yg + pb[nb][1]) * inv7;
        const float pw = pb[nb][2], ph = pb[nb][3];
        const float tb_ = fminf(tcx + tw * 0.5f, pcx + pw * 0.5f)
                        - fmaxf(tcx - tw * 0.5f, pcx - pw * 0.5f);
        const float lr_ = fminf(tcy + th * 0.5f, pcy + ph * 0.5f)
                        - fmaxf(tcy - th * 0.5f, pcy - ph * 0.5f);
        const float inter = (tb_ < 0.0f || lr_ < 0.0f) ? 0.0f : tb_ * lr_;
        iou[nb] = __fdividef(inter, tw * th + pw * ph - inter);
    }

    const int best = (iou[1] > iou[0]) ? 1 : 0;
    const float iou_b  = iou[best];
    const float conf_b = best ? conf1 : conf0;

    const float d0 = pb[best][0] - tox;
    const float d1 = pb[best][1] - toy;
    const float d2 = fsqrt_a(pb[best][2]) - fsqrt_a(tw);
    const float d3 = fsqrt_a(pb[best][3]) - fsqrt_a(th);
    const float coord = d0 * d0 + d1 * d1 + d2 * d2 + d3 * d3;

    const float dc = conf_b - iou_b;
    const float dl = 1.0f - cls_t;
    const float obj_loss   = 5.0f * coord + dc * dc + dl * dl;
    const float noobj_loss = 0.5f * (conf0 * conf0 + conf1 * conf1);
    return (g == 1) ? obj_loss : noobj_loss;
}

__global__ __launch_bounds__(NTHREADS)
void yolo_loss_kernel(const float* __restrict__ pred,
                      const int*   __restrict__ grid,
                      const float* __restrict__ tbox,
                      const int*   __restrict__ tcls,
                      float* __restrict__ out)
{
    // 2 stages * 8 warps * (32 cells * 30 words) = 15360 words = 61440 B
    __shared__ float sp[2 * 8 * 960];

    const int lane = threadIdx.x & 31;
    const int wid  = threadIdx.x >> 5;

    // Issue cp.async for both tiles (2 commit groups per thread).
    #pragma unroll
    for (int st = 0; st < 2; st++) {
        // warp's tile: 32 cells starting at cellbase
        const int cellbase = blockIdx.x * CELLS_PER_BLOCK + st * 256 + wid * 32;
        // float4 base index: cellbase*30/4 ; cellbase is a multiple of 32
        const long f4base = (long)(cellbase >> 1) * 15;
        const float4* src = reinterpret_cast<const float4*>(pred) + f4base;
        float* dstf = sp + (st * 8 + wid) * 960;
        #pragma unroll
        for (int i = 0; i < 8; i++) {
            const int idx = lane + i * 32;              // float4 within 240-f4 tile
            if (idx < 240) {
                const unsigned int da = smem_u32(dstf + idx * 4);
                asm volatile("cp.async.cg.shared.global [%0], [%1], 16;"
                             :: "r"(da), "l"(src + idx));
            }
        }
        asm volatile("cp.async.commit_group;");
    }

    float v;
    {   // tile 0: wait until <=1 group pending (tile0 done), tile1 still in flight
        asm volatile("cp.async.wait_group 1;");
        __syncwarp();
        const int t0 = blockIdx.x * CELLS_PER_BLOCK + wid * 32 + lane;
        const float* p = sp + wid * 960 + lane * 30;
        v = cell_loss(p, t0, grid, tbox, tcls);
    }
    {   // tile 1
        asm volatile("cp.async.wait_group 0;");
        __syncwarp();
        const int t1 = blockIdx.x * CELLS_PER_BLOCK + 256 + wid * 32 + lane;
        const float* p = sp + (8 + wid) * 960 + lane * 30;
        v += cell_loss(p, t1, grid, tbox, tcls);
    }

    // block reduction -> g_partials[blockIdx.x]
    #pragma unroll
    for (int o = 16; o; o >>= 1) v += __shfl_down_sync(0xffffffffu, v, o);
    __shared__ float wsum[NTHREADS / 32];
    __shared__ bool s_last;
    if (lane == 0) wsum[wid] = v;
    __syncthreads();
    if (threadIdx.x < NTHREADS / 32) {
        v = wsum[threadIdx.x];
        #pragma unroll
        for (int o = NTHREADS / 64; o; o >>= 1) v += __shfl_down_sync(0xffu, v, o);
        if (threadIdx.x == 0) {
            g_partials[blockIdx.x] = v;
            __threadfence();
            unsigned int prev = atomicInc(&g_done, NBLOCKS - 1);
            s_last = (prev == NBLOCKS - 1);
        }
    }
    __syncthreads();

    // Last-arriving block: deterministic final reduction
    if (s_last) {
        double acc = 0.0;
        for (int i = threadIdx.x; i < NBLOCKS; i += NTHREADS)
            acc += (double)g_partials[i];
        #pragma unroll
        for (int o = 16; o; o >>= 1) acc += __shfl_down_sync(0xffffffffu, acc, o);
        __shared__ double ws[NTHREADS / 32];
        if (lane == 0 && wid < NTHREADS / 32) ws[wid] = acc;
        __syncthreads();
        if (threadIdx.x == 0) {
            double sum = 0.0;
            #pragma unroll
            for (int i = 0; i < NTHREADS / 32; i++) sum += ws[i];
            out[0] = (float)(sum / 16384.0);
        }
    }
}

extern "C" void kernel_launch(void* const* d_in, const int* in_sizes, int n_in,
                              void* d_out, int out_size)
{
    const float* pred = (const float*)d_in[0];   // (B, 1470) f32
    const int*   grid = (const int*)  d_in[1];   // (B, 7, 7) i32
    const float* tbox = (const float*)d_in[2];   // (B, 7, 7, 4) f32
    const int*   tcls = (const int*)  d_in[3];   // (B, 7, 7) i32
    float* out = (float*)d_out;

    yolo_loss_kernel<<<NBLOCKS, NTHREADS>>>(pred, grid, tbox, tcls, out);
}

// round 8
// speedup vs baseline: 1.4069x; 1.2449x over previous
#include <cuda_runtime.h>
#include <cuda_bf16.h>

// Yolov1 loss — persistent single-wave kernel with continuous cp.async ring.
// B=16384, cells = 802816 = 25088 tiles of 32 cells.
// 444 blocks (148 SM * 3) * 8 warps = 3552 warp-streams; stream s handles tiles
// s, s+3552, s+2*3552, ... (blocks 0..27 get 8 tiles/warp, blocks 28..443 get 7 —
// exactly uniform within each block).
// Cell layout: [0:2) conf, [2:10) boxes (NB,4), [10:30) class logits.

#define NBLOCKS  444
#define NTHREADS 256
#define NSTREAMS (NBLOCKS * 8)   // 3552
#define NTILES   25088

__device__ float g_partials[NBLOCKS];
__device__ unsigned int g_done = 0;   // atomicInc mod NBLOCKS -> self-resetting

__device__ __forceinline__ float fsig(float x) {
    float t;
    asm("tanh.approx.f32 %0, %1;" : "=f"(t) : "f"(x * 0.5f));
    return fmaf(t, 0.5f, 0.5f);
}
__device__ __forceinline__ float fsqrt_a(float x) {
    float r;
    asm("sqrt.approx.f32 %0, %1;" : "=f"(r) : "f"(x));
    return r;
}
__device__ __forceinline__ unsigned int smem_u32(const void* p) {
    return (unsigned int)__cvta_generic_to_shared(p);
}

// One cell's loss. p = 30 floats in smem; target data already in registers.
__device__ __forceinline__ float cell_loss(const float* __restrict__ p, int t,
                                           float4 tb, int g, int tc)
{
    const int s = t % 49;
    const float xg = (float)(s % 7);
    const float yg = (float)(s / 7);
    const float inv7 = 1.0f / 7.0f;
    const float tox = tb.x, toy = tb.y, tw = tb.z, th = tb.w;

    const float conf0 = fsig(p[0]);
    const float conf1 = fsig(p[1]);
    float pb[2][4];
    #pragma unroll
    for (int nb = 0; nb < 2; nb++)
        #pragma unroll
        for (int k = 0; k < 4; k++)
            pb[nb][k] = fsig(p[2 + nb * 4 + k]);

    float esum = 0.0f, et = 0.0f;
    #pragma unroll
    for (int j = 0; j < 20; j++) {
        const float e = __expf(p[10 + j]);
        esum += e;
        if (j == tc) et = e;
    }
    const float cls_t = __fdividef(et, esum);

    const float tcx = (xg + tox) * inv7;
    const float tcy = (yg + toy) * inv7;
    float iou[2];
    #pragma unroll
    for (int nb = 0; nb < 2; nb++) {
        const float pcx = (xg + pb[nb][0]) * inv7;
        const float pcy = (yg + pb[nb][1]) * inv7;
        const float pw = pb[nb][2], ph = pb[nb][3];
        const float tb_ = fminf(tcx + tw * 0.5f, pcx + pw * 0.5f)
                        - fmaxf(tcx - tw * 0.5f, pcx - pw * 0.5f);
        const float lr_ = fminf(tcy + th * 0.5f, pcy + ph * 0.5f)
                        - fmaxf(tcy - th * 0.5f, pcy - ph * 0.5f);
        const float inter = (tb_ < 0.0f || lr_ < 0.0f) ? 0.0f : tb_ * lr_;
        iou[nb] = __fdividef(inter, tw * th + pw * ph - inter);
    }

    const int best = (iou[1] > iou[0]) ? 1 : 0;
    const float iou_b  = iou[best];
    const float conf_b = best ? conf1 : conf0;

    const float d0 = pb[best][0] - tox;
    const float d1 = pb[best][1] - toy;
    const float d2 = fsqrt_a(pb[best][2]) - fsqrt_a(tw);
    const float d3 = fsqrt_a(pb[best][3]) - fsqrt_a(th);
    const float coord = d0 * d0 + d1 * d1 + d2 * d2 + d3 * d3;

    const float dc = conf_b - iou_b;
    const float dl = 1.0f - cls_t;
    const float obj_loss   = 5.0f * coord + dc * dc + dl * dl;
    const float noobj_loss = 0.5f * (conf0 * conf0 + conf1 * conf1);
    return (g == 1) ? obj_loss : noobj_loss;
}

__global__ __launch_bounds__(NTHREADS, 3)
void yolo_loss_kernel(const float* __restrict__ pred,
                      const int*   __restrict__ grid,
                      const float* __restrict__ tbox,
                      const int*   __restrict__ tcls,
                      float* __restrict__ out)
{
    // 2 stages * 8 warps * (32 cells * 30 words) = 61440 B
    __shared__ float sp[2 * 8 * 960];

    const int lane = threadIdx.x & 31;
    const int wid  = threadIdx.x >> 5;
    const int stream = blockIdx.x * 8 + wid;

    float* const s0 = sp + wid * 960;
    float* const s1 = sp + (8 + wid) * 960;
    const float4* const tbox4 = reinterpret_cast<const float4*>(tbox);
    const float4* const pred4 = reinterpret_cast<const float4*>(pred);

    // ---- prefetch tile 0 (pred via cp.async; targets via LDG) ----
    {
        const float4* src = pred4 + (long)stream * 240;
        #pragma unroll
        for (int i = 0; i < 8; i++) {
            const int idx = lane + i * 32;
            if (idx < 240) {
                const unsigned int da = smem_u32(s0 + idx * 4);
                asm volatile("cp.async.cg.shared.global [%0], [%1], 16;"
                             :: "r"(da), "l"(src + idx));
            }
        }
        asm volatile("cp.async.commit_group;");
    }
    int c0 = stream * 32 + lane;
    float4 tb = __ldg(tbox4 + c0);
    int    g  = __ldg(grid + c0);
    int    tc = __ldg(tcls + c0);

    float v = 0.0f;
    int stage = 0;

    for (int it = 0; ; it++) {
        const int tn = stream + (it + 1) * NSTREAMS;
        const bool validn = (tn < NTILES);

        // issue prefetch of next pred tile into the alternate stage
        if (validn) {
            float* dst = stage ? s0 : s1;
            const float4* src = pred4 + (long)tn * 240;
            #pragma unroll
            for (int i = 0; i < 8; i++) {
                const int idx = lane + i * 32;
                if (idx < 240) {
                    const unsigned int da = smem_u32(dst + idx * 4);
                    asm volatile("cp.async.cg.shared.global [%0], [%1], 16;"
                                 :: "r"(da), "l"(src + idx));
                }
            }
        }
        asm volatile("cp.async.commit_group;");   // always (keeps group count uniform)

        // register-prefetch next targets (overlaps with current compute)
        float4 tbn; int gn = 0, tcn = 0;
        if (validn) {
            const int cn = tn * 32 + lane;
            tbn = __ldg(tbox4 + cn);
            gn  = __ldg(grid + cn);
            tcn = __ldg(tcls + cn);
        }

        if (validn) asm volatile("cp.async.wait_group 1;");
        else        asm volatile("cp.async.wait_group 0;");
        __syncwarp();

        const float* p = (stage ? s1 : s0) + lane * 30;
        const int t_cell = (stream + it * NSTREAMS) * 32 + lane;
        v += cell_loss(p, t_cell, tb, g, tc);

        if (!validn) break;
        tb = tbn; g = gn; tc = tcn;
        stage ^= 1;
    }

    // ---- block reduction -> g_partials[blockIdx.x] ----
    #pragma unroll
    for (int o = 16; o; o >>= 1) v += __shfl_down_sync(0xffffffffu, v, o);
    __shared__ float wsum[NTHREADS / 32];
    __shared__ bool s_last;
    if (lane == 0) wsum[wid] = v;
    __syncthreads();
    if (threadIdx.x < NTHREADS / 32) {
        v = wsum[threadIdx.x];
        #pragma unroll
        for (int o = NTHREADS / 64; o; o >>= 1) v += __shfl_down_sync(0xffu, v, o);
        if (threadIdx.x == 0) {
            g_partials[blockIdx.x] = v;
            __threadfence();
            unsigned int prev = atomicInc(&g_done, NBLOCKS - 1);
            s_last = (prev == NBLOCKS - 1);
        }
    }
    __syncthreads();

    // ---- last-arriving block: deterministic final reduction ----
    if (s_last) {
        double acc = 0.0;
        for (int i = threadIdx.x; i < NBLOCKS; i += NTHREADS)
            acc += (double)g_partials[i];
        #pragma unroll
        for (int o = 16; o; o >>= 1) acc += __shfl_down_sync(0xffffffffu, acc, o);
        __shared__ double ws[NTHREADS / 32];
        if (lane == 0) ws[wid] = acc;
        __syncthreads();
        if (threadIdx.x == 0) {
            double sum = 0.0;
            #pragma unroll
            for (int i = 0; i < NTHREADS / 32; i++) sum += ws[i];
            out[0] = (float)(sum / 16384.0);
        }
    }
}

extern "C" void kernel_launch(void* const* d_in, const int* in_sizes, int n_in,
                              void* d_out, int out_size)
{
    const float* pred = (const float*)d_in[0];   // (B, 1470) f32
    const int*   grid = (const int*)  d_in[1];   // (B, 7, 7) i32
    const float* tbox = (const float*)d_in[2];   // (B, 7, 7, 4) f32
    const int*   tcls = (const int*)  d_in[3];   // (B, 7, 7) i32
    float* out = (float*)d_out;

    yolo_loss_kernel<<<NBLOCKS, NTHREADS>>>(pred, grid, tbox, tcls, out);
}